// round 14
// baseline (speedup 1.0000x reference)
#include <cuda_runtime.h>
#include <cstdint>

// Problem sizes (fixed by the reference setup_inputs)
#define Bn 16
#define Nn 1024
#define Mn 4096
#define Dd 64

#define IBLK 128                 // DP consumption granularity (rows) == GTI
#define NIB  (Nn / IBLK)         // 8 i-blocks
#define GTI  128                 // GEMM tile rows (i)
#define GTJ  128                 // GEMM tile cols (j)
#define NJT  (Mn / GTJ)          // 32 j-tiles per (b, iblk)
#define KC   16                  // k-chunk
#define NBAND (Nn / 32)          // 32 backtrack bands
#define NDPC 32                  // DP CTAs total (2 per batch)

// Static device scratch (allocation anywhere is forbidden).
__device__ float          g_C[67108864];       // [B][N][M] fp32, 256 MB
__device__ unsigned char  g_choice[67108864];  // [B] tiled 32x32 choice bytes, 64 MB
__device__ int            g_cnt[Bn * NIB];     // tile-completion counters
__device__ int            g_j0[Bn];            // per-batch argmin column of last row
__device__ unsigned short g_exitJ[Bn][NBAND][Mn]; // band exit columns, 4 MB
__device__ float4         g_hand[Bn][256];     // cross-CTA scan handoff ring
__device__ int            g_handProg[Bn];      // cross-CTA consumer progress
__device__ uint4          g_part[Bn][2];       // per-CTA argmin partials

__device__ __forceinline__ float finf() { return __int_as_float(0x7f800000); }

// ---- packed f32x2 helpers (sm_103a: 2x fp32 throughput via fma.rn.f32x2) ----
__device__ __forceinline__ unsigned long long pk2(float lo, float hi) {
    unsigned long long r;
    asm("mov.b64 %0, {%1, %2};" : "=l"(r) : "f"(lo), "f"(hi));
    return r;
}
__device__ __forceinline__ void upk2(unsigned long long v, float& lo, float& hi) {
    asm("mov.b64 {%0, %1}, %2;" : "=f"(lo), "=f"(hi) : "l"(v));
}
__device__ __forceinline__ unsigned long long ffma2(unsigned long long a,
                                                    unsigned long long b,
                                                    unsigned long long c) {
    unsigned long long d;
    asm("fma.rn.f32x2 %0, %1, %2, %3;" : "=l"(d) : "l"(a), "l"(b), "l"(c));
    return d;
}

// ---- volatile 16B packet helpers (single HW 128-bit access, tag in .w) ----
__device__ __forceinline__ void ld_pkt(const void* p, float& S, float& M, unsigned& tag) {
    float d;
    asm volatile("ld.volatile.v4.b32 {%0,%1,%2,%3}, [%4];"
                 : "=f"(S), "=f"(M), "=f"(d), "=r"(tag) : "l"(p) : "memory");
}
__device__ __forceinline__ void st_pkt(void* p, float S, float M, unsigned tag) {
    asm volatile("st.volatile.v4.b32 [%0], {%1,%2,%3,%4};"
                 :: "l"(p), "f"(S), "f"(M), "f"(0.f), "r"(tag) : "memory");
}
__device__ __forceinline__ void ld_pktu(const void* p, unsigned& a, unsigned& b2, unsigned& tag) {
    unsigned d;
    asm volatile("ld.volatile.v4.b32 {%0,%1,%2,%3}, [%4];"
                 : "=r"(a), "=r"(b2), "=r"(d), "=r"(tag) : "l"(p) : "memory");
}
__device__ __forceinline__ void st_pktu(void* p, unsigned a, unsigned b2, unsigned tag) {
    asm volatile("st.volatile.v4.b32 [%0], {%1,%2,%3,%4};"
                 :: "l"(p), "r"(a), "r"(b2), "r"(0u), "r"(tag) : "memory");
}

// tiled 32x32 choice address
__device__ __forceinline__ size_t chaddr(int i, int j) {
    return (size_t)((i >> 5) * (Mn / 32) + (j >> 5)) * 1024
         + (size_t)(i & 31) * 32 + (j & 31);
}

__global__ void zero_cnt_kernel() {
    int t = threadIdx.x;
    if (t < Bn * NIB) g_cnt[t] = 0;
    if (t < Bn) g_handProg[t] = 0;
    if (t < Bn * 2) ((uint4*)g_part)[t] = make_uint4(0, 0, 0, 0);
    for (int i = t; i < Bn * 256; i += 1024)
        ((float4*)g_hand)[i] = make_float4(0.f, 0.f, 0.f, 0.f);
}

// ---------------------------------------------------------------------------
// Fused kernel.
//  blocks [0,32):        DP CTAs, 2 per batch (b = blk>>1, col half c = blk&1),
//                        warp-pipelined scan chain, NO CTA barriers in row loop.
//  blocks [32, 32+4096): GEMM tile CTAs (128x128), i-block outermost so C is
//                        produced in DP consumption order.
// ---------------------------------------------------------------------------
__global__ void __launch_bounds__(1024, 1)
fused_kernel(const float* __restrict__ x, const float* __restrict__ y,
             const float* __restrict__ x_t, float* __restrict__ out) {
    __shared__ __align__(16) unsigned char smem_raw[17920];
    const int t = threadIdx.x;
    const float INF = finf();

    if (blockIdx.x >= NDPC) {
        // =================== GEMM CTA (128x128 tile, 4x4 per thread) ========
        float* xs  = (float*)smem_raw;           // [KC][GTI+4]
        float* ys  = xs + KC * (GTI + 4);        // [KC][GTJ+4]
        float* x2s = ys + KC * (GTJ + 4);        // [GTI]
        float* y2s = x2s + GTI;                  // [GTJ]

        int gid  = blockIdx.x - NDPC;
        int iblk = gid >> 9;                     // 0..7  (outermost -> in-order)
        int rem  = gid & 511;
        int b    = rem >> 5;                     // 0..15
        int jblk = rem & 31;                     // 0..31
        int i0 = iblk * GTI, j0 = jblk * GTJ;

        const int c4 = (t & 31) * 4;             // cols c4..c4+3
        const int r4 = (t >> 5) * 4;             // rows r4..r4+3

        unsigned long long acc[4][2];
#pragma unroll
        for (int r = 0; r < 4; r++) { acc[r][0] = 0ull; acc[r][1] = 0ull; }

        float x2a = 0.f, y2a = 0.f;

        for (int kc = 0; kc < Dd; kc += KC) {
            if (t < 512) {                       // x tile: 128 rows x 4 float4
                int row = t >> 2, cc4 = (t & 3) * 4;
                float4 v = *reinterpret_cast<const float4*>(
                    x + ((size_t)b * Nn + i0 + row) * Dd + kc + cc4);
                xs[(cc4 + 0) * (GTI + 4) + row] = v.x;
                xs[(cc4 + 1) * (GTI + 4) + row] = v.y;
                xs[(cc4 + 2) * (GTI + 4) + row] = v.z;
                xs[(cc4 + 3) * (GTI + 4) + row] = v.w;
            } else {                             // y tile
                int u = t - 512;
                int row = u >> 2, cc4 = (u & 3) * 4;
                float4 v = *reinterpret_cast<const float4*>(
                    y + ((size_t)b * Mn + j0 + row) * Dd + kc + cc4);
                ys[(cc4 + 0) * (GTJ + 4) + row] = v.x;
                ys[(cc4 + 1) * (GTJ + 4) + row] = v.y;
                ys[(cc4 + 2) * (GTJ + 4) + row] = v.z;
                ys[(cc4 + 3) * (GTJ + 4) + row] = v.w;
            }
            __syncthreads();

            if (t < GTI) {
#pragma unroll
                for (int k = 0; k < KC; k++) {
                    float v = xs[k * (GTI + 4) + t];
                    x2a = fmaf(v, v, x2a);
                }
            } else if (t < GTI + GTJ) {
                int j = t - GTI;
#pragma unroll
                for (int k = 0; k < KC; k++) {
                    float v = ys[k * (GTJ + 4) + j];
                    y2a = fmaf(v, v, y2a);
                }
            }

#pragma unroll
            for (int k = 0; k < KC; k++) {
                float4 av = *reinterpret_cast<const float4*>(&xs[k * (GTI + 4) + r4]);
                float4 b0 = *reinterpret_cast<const float4*>(&ys[k * (GTJ + 4) + c4]);
                unsigned long long b01 = pk2(b0.x, b0.y);
                unsigned long long b23 = pk2(b0.z, b0.w);
                unsigned long long a0 = pk2(av.x, av.x);
                unsigned long long a1 = pk2(av.y, av.y);
                unsigned long long a2 = pk2(av.z, av.z);
                unsigned long long a3 = pk2(av.w, av.w);
                acc[0][0] = ffma2(a0, b01, acc[0][0]); acc[0][1] = ffma2(a0, b23, acc[0][1]);
                acc[1][0] = ffma2(a1, b01, acc[1][0]); acc[1][1] = ffma2(a1, b23, acc[1][1]);
                acc[2][0] = ffma2(a2, b01, acc[2][0]); acc[2][1] = ffma2(a2, b23, acc[2][1]);
                acc[3][0] = ffma2(a3, b01, acc[3][0]); acc[3][1] = ffma2(a3, b23, acc[3][1]);
            }
            __syncthreads();
        }

        if (t < GTI) x2s[t] = x2a;
        else if (t < GTI + GTJ) y2s[t - GTI] = y2a;
        __syncthreads();

#pragma unroll
        for (int r = 0; r < 4; r++) {
            float xr = x2s[r4 + r];
            float a0, a1, a2, a3;
            upk2(acc[r][0], a0, a1); upk2(acc[r][1], a2, a3);
            float4 o;
            o.x = xr + y2s[c4 + 0] - 2.f * a0;
            o.y = xr + y2s[c4 + 1] - 2.f * a1;
            o.z = xr + y2s[c4 + 2] - 2.f * a2;
            o.w = xr + y2s[c4 + 3] - 2.f * a3;
            *reinterpret_cast<float4*>(
                g_C + ((size_t)b * Nn + i0 + r4 + r) * Mn + j0 + c4) = o;
        }

        // publish tile completion (release)
        __threadfence();
        __syncthreads();
        if (t == 0) atomicAdd(&g_cnt[b * NIB + iblk], 1);
        return;
    }

    // =================== DP CTA (batch b, column half c) ===================
    const int b = blockIdx.x >> 1;
    const int c = blockIdx.x & 1;

    if (t >= 512) {
        // helper threads: copy w_ts (each CTA copies its half), then exit.
        float* w_ts = out + Bn;
        int idx = c * 512 + (t - 512);
        w_ts[b * Nn + idx] = x_t[b * Nn + idx];
        return;
    }

    float4* slots     = (float4*)smem_raw;            // [16][32] packet rings
    int*    consProgA = (int*)(smem_raw + 8192);      // [16]
    uint4*  argSlots  = (uint4*)(smem_raw + 8256);    // [16]

    const int lane = t & 31, w = t >> 5;
    const int j4 = c * 2048 + t * 4;                  // global column base
    const float* Cb = g_C + (size_t)b * Nn * Mn;
    unsigned char* chb = g_choice + (size_t)b * Nn * Mn;

    // init own structures, then worker-only named barrier
    slots[w * 32 + lane] = make_float4(0.f, 0.f, 0.f, 0.f);
    if (lane == 0) { consProgA[w] = 0; argSlots[w] = make_uint4(0, 0, 0, 0); }
    asm volatile("bar.sync 1, 512;" ::: "memory");

    const bool isCons = !(w == 0 && c == 0);          // has upstream producer
    const bool isProd = !(w == 15 && c == 1);         // has downstream consumer
    const char* srcBase = (w == 0) ? (const char*)&g_hand[b][0]
                                   : (const char*)&slots[(w - 1) * 32];
    const int srcMask = (w == 0) ? 255 : 31;
    char* dstBase = (w == 15) ? (char*)&g_hand[b][0] : (char*)&slots[w * 32];
    const int dstMask = (w == 15) ? 255 : 31;

    // gate i-block 0 (per-warp acquire)
    if (lane == 0) while (atomicAdd(&g_cnt[b * NIB + 0], 0) < NJT) __nanosleep(200);
    __syncwarp();
    __threadfence();

    // Row 0: D = C. Register state: pD = D[i-1] own cols; carry = D[i-1][j4-1].
    float4 cc0 = *reinterpret_cast<const float4*>(Cb + j4);
    float pD0 = cc0.x, pD1 = cc0.y, pD2 = cc0.z, pD3 = cc0.w;
    float carry = (j4 == 0) ? INF : Cb[j4 - 1];

    float4 cnA = *reinterpret_cast<const float4*>(Cb + (size_t)1 * Mn + j4);
    float4 cnB = *reinterpret_cast<const float4*>(Cb + (size_t)2 * Mn + j4);

    for (int i = 1; i < Nn; i++) {
        float4 cc;
        if ((i & (IBLK - 1)) == 0) {
            if (lane == 0) while (atomicAdd(&g_cnt[b * NIB + (i >> 7)], 0) < NJT) __nanosleep(200);
            __syncwarp();
            __threadfence();
            cc  = *reinterpret_cast<const float4*>(Cb + (size_t)i * Mn + j4);
            cnA = *reinterpret_cast<const float4*>(Cb + (size_t)(i + 1) * Mn + j4);
            cnB = *reinterpret_cast<const float4*>(Cb + (size_t)(i + 2) * Mn + j4);
        } else {
            cc = cnA; cnA = cnB;
            int nf = i + 2;
            if (nf < Nn && (i & (IBLK - 1)) <= IBLK - 3)
                cnB = *reinterpret_cast<const float4*>(Cb + (size_t)nf * Mn + j4);
        }

        // speculative upstream-packet load (hidden under local work + scan)
        float qS = 0.f, qM = INF; unsigned tag = (unsigned)i;
        const char* sp = nullptr;
        if (isCons) { sp = srcBase + (size_t)(i & srcMask) * 16; ld_pkt(sp, qS, qM, tag); }

        // producer backpressure (ring-slot safety), amortized
        if ((i & 15) == 0 && isProd) {
            if (w < 15) {
                while (*((volatile int*)&consProgA[w + 1]) < i - 16) __nanosleep(100);
            } else if ((i & 63) == 0) {   // w==15, c==0 -> gmem ring
                while (*((volatile int*)&g_handProg[b]) < i - 128) __nanosleep(200);
            }
        }

        const float up0 = pD0, up1 = pD1, up2 = pD2, up3 = pD3, dg0 = carry;

        float a0 = fminf(up0, dg0) + cc.x;
        float a1 = fminf(up1, up0) + cc.y;
        float a2 = fminf(up2, up1) + cc.z;
        float a3 = fminf(up3, up2) + cc.w;

        float s0 = cc.x, s1 = s0 + cc.y, s2 = s1 + cc.z, s3 = s2 + cc.w;
        float m0 = a0 - s0;
        float m1 = fminf(m0, a1 - s1);
        float m2 = fminf(m1, a2 - s2);
        float m3 = fminf(m2, a3 - s3);

        // warp-level inclusive pair scan: (s,m) op (s',m') = (s+s', min(m, m'-s))
        float S = s3, Mv = m3;
#pragma unroll
        for (int d = 1; d < 32; d <<= 1) {
            float so = __shfl_up_sync(0xffffffffu, S, d);
            float mo = __shfl_up_sync(0xffffffffu, Mv, d);
            if (lane >= d) { Mv = fminf(mo, Mv - so); S = S + so; }
        }
        float sE = __shfl_up_sync(0xffffffffu, S, 1);
        float mE = __shfl_up_sync(0xffffffffu, Mv, 1);
        if (lane == 0) { sE = 0.f; mE = INF; }

        // receive upstream exclusive aggregate Q
        if (isCons) {
            while (tag != (unsigned)i) { __nanosleep(40); ld_pkt(sp, qS, qM, tag); }
            if ((i & 15) == 0 && lane == 0) {      // consumer progress
                if (w == 0 && c == 1) { if ((i & 63) == 0) *((volatile int*)&g_handProg[b]) = i; }
                else *((volatile int*)&consProgA[w]) = i;
            }
        }

        // publish downstream ASAP (lane 31 holds warp-inclusive aggregates)
        if (isProd && lane == 31) {
            float oS = qS + S;
            float oM = fminf(qM, Mv - qS);
            st_pkt(dstBase + (size_t)(i & dstMask) * 16, oS, oM, (unsigned)i);
        }

        float offS = qS + sE;               // exclusive prefix sum (global)
        float PexM = fminf(qM, mE - qS);    // exclusive prefix min of (a - S)

        float D0 = offS + s0 + fminf(PexM, m0 - offS);
        float D1 = offS + s1 + fminf(PexM, m1 - offS);
        float D2 = offS + s2 + fminf(PexM, m2 - offS);
        float D3 = offS + s3 + fminf(PexM, m3 - offS);

        float dl0 = offS + PexM;            // == D[i][j4-1] (INF at global col 0)

        // choice codes: 0=diag, 1=up, 2=left (tie priority diag > up > left)
        unsigned char q0 = (dg0 <= up0 && dg0 <= dl0) ? 0 : ((up0 <= dl0) ? 1 : 2);
        unsigned char q1 = (up0 <= up1 && up0 <= D0)  ? 0 : ((up1 <= D0)  ? 1 : 2);
        unsigned char q2 = (up1 <= up2 && up1 <= D1)  ? 0 : ((up2 <= D1)  ? 1 : 2);
        unsigned char q3 = (up2 <= up3 && up2 <= D2)  ? 0 : ((up3 <= D2)  ? 1 : 2);

        *reinterpret_cast<uchar4*>(chb + chaddr(i, j4)) = make_uchar4(q0, q1, q2, q3);

        pD0 = D0; pD1 = D1; pD2 = D2; pD3 = D3;
        carry = dl0;
    }

    // argmin (first occurrence) over last row, register -> warp -> CTA -> pair
    float bv = pD0; int bj = j4;
    if (pD1 < bv) { bv = pD1; bj = j4 + 1; }
    if (pD2 < bv) { bv = pD2; bj = j4 + 2; }
    if (pD3 < bv) { bv = pD3; bj = j4 + 3; }
#pragma unroll
    for (int d = 16; d > 0; d >>= 1) {
        float ov = __shfl_xor_sync(0xffffffffu, bv, d);
        int   oj = __shfl_xor_sync(0xffffffffu, bj, d);
        if (ov < bv || (ov == bv && oj < bj)) { bv = ov; bj = oj; }
    }
    if (lane == 0) st_pktu(&argSlots[w], __float_as_uint(bv), (unsigned)bj, 1u);

    if (w == 0) {
        float v = INF; int jj = 0x7fffffff;
        if (lane < 16) {
            unsigned a, b2, tg;
            ld_pktu(&argSlots[lane], a, b2, tg);
            while (tg != 1u) { __nanosleep(50); ld_pktu(&argSlots[lane], a, b2, tg); }
            v = __uint_as_float(a); jj = (int)b2;
        }
#pragma unroll
        for (int d = 16; d > 0; d >>= 1) {
            float ov = __shfl_xor_sync(0xffffffffu, v, d);
            int   oj = __shfl_xor_sync(0xffffffffu, jj, d);
            if (ov < v || (ov == v && oj < jj)) { v = ov; jj = oj; }
        }
        if (lane == 0) {
            st_pktu(&g_part[b][c], __float_as_uint(v), (unsigned)jj, 1u);
            if (c == 0) {
                unsigned a, b2, tg;
                ld_pktu(&g_part[b][1], a, b2, tg);
                while (tg != 1u) { __nanosleep(100); ld_pktu(&g_part[b][1], a, b2, tg); }
                float v1 = __uint_as_float(a);
                if (v1 < v) { v = v1; jj = (int)b2; }   // ties keep c0 (smaller j)
                out[b] = v;
                g_j0[b] = jj;
            }
        }
    }
}

// ---------------------------------------------------------------------------
// Band-parallel backtrack precompute: for every (batch, band tb in [1,31],
// entry column j) walk the 32-row segment; record exit column.
// ---------------------------------------------------------------------------
__global__ void __launch_bounds__(256) bandwalk_kernel() {
    const int tb = blockIdx.x + 1;               // 1..31
    const int b  = blockIdx.y;
    const unsigned char* chb = g_choice + (size_t)b * Nn * Mn;
    const int iTop  = tb * 32 + 31;
    const int iStop = tb * 32 - 1;               // walk while i > iStop

#pragma unroll
    for (int k = 0; k < Mn / 256; k++) {
        int j = threadIdx.x + k * 256;
        int jin = j;
        int i = iTop;
        while (i > iStop) {
            unsigned char ch = __ldg(chb + chaddr(i, j));
            if (ch == 0)      { --i; --j; }
            else if (ch == 1) { --i; }
            else              { --j; }
        }
        g_exitJ[b][tb][jin] = (unsigned short)j;
    }
}

// ---------------------------------------------------------------------------
// Finalize: per batch, chain band entry columns through the exit table, then
// 32 parallel segment re-walks emit w_vs.
// ---------------------------------------------------------------------------
__global__ void __launch_bounds__(64) finalize_kernel(const float* __restrict__ y_t,
                                                      float* __restrict__ out) {
    __shared__ int entry[NBAND];
    const int b = blockIdx.x, t = threadIdx.x;
    float* w_vs = out + Bn + Bn * Nn;
    const float* ytb = y_t + (size_t)b * Mn;
    const unsigned char* chb = g_choice + (size_t)b * Nn * Mn;

    if (t == 0) {
        int j = g_j0[b];
        w_vs[b * Nn + (Nn - 1)] = ytb[j];        // row 1023 entry
        entry[NBAND - 1] = j;
        for (int tb = NBAND - 1; tb >= 1; --tb) {
            j = g_exitJ[b][tb][j];
            entry[tb - 1] = j;
        }
    }
    __syncthreads();

    if (t < NBAND) {
        const int tb = t;
        int i = tb * 32 + 31;
        int j = entry[tb];
        const int iStop = (tb == 0) ? 0 : (tb * 32 - 1);
        while (i > iStop) {
            unsigned char ch = __ldg(chb + chaddr(i, j));
            if (ch == 2) { --j; }
            else {
                if (ch == 0) --j;
                --i;
                w_vs[b * Nn + i] = ytb[j];
            }
        }
    }
}

// ---------------------------------------------------------------------------
extern "C" void kernel_launch(void* const* d_in, const int* in_sizes, int n_in,
                              void* d_out, int out_size) {
    const float* x   = (const float*)d_in[0];   // [16,1024,64]
    const float* y   = (const float*)d_in[1];   // [16,4096,64]
    const float* x_t = (const float*)d_in[2];   // [16,1024]
    const float* y_t = (const float*)d_in[3];   // [16,4096]
    float* out = (float*)d_out;                 // 16 + 16384 + 16384 floats

    zero_cnt_kernel<<<1, 1024>>>();
    fused_kernel<<<NDPC + Bn * NIB * NJT, 1024>>>(x, y, x_t, out);
    bandwalk_kernel<<<dim3(NBAND - 1, Bn), 256>>>();
    finalize_kernel<<<Bn, 64>>>(y_t, out);
}

// round 16
// speedup vs baseline: 2.0861x; 2.0861x over previous
#include <cuda_runtime.h>
#include <cstdint>

// Problem sizes (fixed by the reference setup_inputs)
#define Bn 16
#define Nn 1024
#define Mn 4096
#define Dd 64

#define IBLK 128                 // DP consumption granularity (rows) == GTI
#define NIB  (Nn / IBLK)         // 8 i-blocks
#define GTI  128                 // GEMM tile rows (i)
#define GTJ  128                 // GEMM tile cols (j)
#define NJT  (Mn / GTJ)          // 32 j-tiles per (b, iblk)
#define KC   16                  // k-chunk
#define NBAND (Nn / 32)          // 32 backtrack bands
#define NDPC 32                  // DP CTAs total (2 per batch)

// Static device scratch (allocation anywhere is forbidden).
__device__ float          g_C[67108864];       // [B][N][M] fp32, 256 MB
__device__ unsigned char  g_choice[67108864];  // [B] tiled 32x32 choice bytes, 64 MB
__device__ int            g_cnt[Bn * NIB];     // tile-completion counters
__device__ int            g_j0[Bn];            // per-batch argmin column of last row
__device__ unsigned short g_exitJ[Bn][NBAND][Mn]; // band exit columns, 4 MB
__device__ float4         g_hand[Bn][256];     // cross-CTA row-aggregate ring
__device__ int            g_handProg[Bn];      // cross-CTA consumer progress
__device__ uint4          g_part[Bn][2];       // per-CTA argmin partials

__device__ __forceinline__ float finf() { return __int_as_float(0x7f800000); }

// ---- packed f32x2 helpers (sm_103a: 2x fp32 throughput via fma.rn.f32x2) ----
__device__ __forceinline__ unsigned long long pk2(float lo, float hi) {
    unsigned long long r;
    asm("mov.b64 %0, {%1, %2};" : "=l"(r) : "f"(lo), "f"(hi));
    return r;
}
__device__ __forceinline__ void upk2(unsigned long long v, float& lo, float& hi) {
    asm("mov.b64 {%0, %1}, %2;" : "=f"(lo), "=f"(hi) : "l"(v));
}
__device__ __forceinline__ unsigned long long ffma2(unsigned long long a,
                                                    unsigned long long b,
                                                    unsigned long long c) {
    unsigned long long d;
    asm("fma.rn.f32x2 %0, %1, %2, %3;" : "=l"(d) : "l"(a), "l"(b), "l"(c));
    return d;
}

// ---- volatile 16B packet helpers (single HW 128-bit access, tag in .w) ----
__device__ __forceinline__ void ld_pkt(const void* p, float& S, float& M, unsigned& tag) {
    float d;
    asm volatile("ld.volatile.v4.b32 {%0,%1,%2,%3}, [%4];"
                 : "=f"(S), "=f"(M), "=f"(d), "=r"(tag) : "l"(p) : "memory");
}
__device__ __forceinline__ void st_pkt(void* p, float S, float M, unsigned tag) {
    asm volatile("st.volatile.v4.b32 [%0], {%1,%2,%3,%4};"
                 :: "l"(p), "f"(S), "f"(M), "f"(0.f), "r"(tag) : "memory");
}
__device__ __forceinline__ void ld_pktu(const void* p, unsigned& a, unsigned& b2, unsigned& tag) {
    unsigned d;
    asm volatile("ld.volatile.v4.b32 {%0,%1,%2,%3}, [%4];"
                 : "=r"(a), "=r"(b2), "=r"(d), "=r"(tag) : "l"(p) : "memory");
}
__device__ __forceinline__ void st_pktu(void* p, unsigned a, unsigned b2, unsigned tag) {
    asm volatile("st.volatile.v4.b32 [%0], {%1,%2,%3,%4};"
                 :: "l"(p), "r"(a), "r"(b2), "r"(0u), "r"(tag) : "memory");
}

// tiled 32x32 choice address
__device__ __forceinline__ size_t chaddr(int i, int j) {
    return (size_t)((i >> 5) * (Mn / 32) + (j >> 5)) * 1024
         + (size_t)(i & 31) * 32 + (j & 31);
}

__global__ void zero_cnt_kernel() {
    int t = threadIdx.x;
    if (t < Bn * NIB) g_cnt[t] = 0;
    if (t < Bn) g_handProg[t] = 0;
    if (t < Bn * 2) ((uint4*)g_part)[t] = make_uint4(0, 0, 0, 0);
    for (int i = t; i < Bn * 256; i += 1024)
        ((float4*)g_hand)[i] = make_float4(0.f, 0.f, 0.f, 0.f);
}

// ---------------------------------------------------------------------------
// Fused kernel.
//  blocks [0,32):        DP CTAs, 2 per batch (b = blk>>1, col half c = blk&1).
//                        Intra-CTA: barrier scan (proven R9 scheme, 16 warps).
//                        Inter-CTA: ONE gmem packet per row, spin-polled by t0.
//  blocks [32, 32+4096): GEMM tile CTAs (128x128), i-block outermost.
// ---------------------------------------------------------------------------
__global__ void __launch_bounds__(1024, 1)
fused_kernel(const float* __restrict__ x, const float* __restrict__ y,
             const float* __restrict__ x_t, float* __restrict__ out) {
    __shared__ __align__(16) unsigned char smem_raw[17920];
    const int t = threadIdx.x;
    const float INF = finf();

    if (blockIdx.x >= NDPC) {
        // =================== GEMM CTA (128x128 tile, 4x4 per thread) ========
        float* xs  = (float*)smem_raw;           // [KC][GTI+4]
        float* ys  = xs + KC * (GTI + 4);        // [KC][GTJ+4]
        float* x2s = ys + KC * (GTJ + 4);        // [GTI]
        float* y2s = x2s + GTI;                  // [GTJ]

        int gid  = blockIdx.x - NDPC;
        int iblk = gid >> 9;                     // 0..7  (outermost -> in-order)
        int rem  = gid & 511;
        int b    = rem >> 5;                     // 0..15
        int jblk = rem & 31;                     // 0..31
        int i0 = iblk * GTI, j0 = jblk * GTJ;

        const int c4 = (t & 31) * 4;             // cols c4..c4+3
        const int r4 = (t >> 5) * 4;             // rows r4..r4+3

        unsigned long long acc[4][2];
#pragma unroll
        for (int r = 0; r < 4; r++) { acc[r][0] = 0ull; acc[r][1] = 0ull; }

        float x2a = 0.f, y2a = 0.f;

        for (int kc = 0; kc < Dd; kc += KC) {
            if (t < 512) {                       // x tile: 128 rows x 4 float4
                int row = t >> 2, cc4 = (t & 3) * 4;
                float4 v = *reinterpret_cast<const float4*>(
                    x + ((size_t)b * Nn + i0 + row) * Dd + kc + cc4);
                xs[(cc4 + 0) * (GTI + 4) + row] = v.x;
                xs[(cc4 + 1) * (GTI + 4) + row] = v.y;
                xs[(cc4 + 2) * (GTI + 4) + row] = v.z;
                xs[(cc4 + 3) * (GTI + 4) + row] = v.w;
            } else {                             // y tile
                int u = t - 512;
                int row = u >> 2, cc4 = (u & 3) * 4;
                float4 v = *reinterpret_cast<const float4*>(
                    y + ((size_t)b * Mn + j0 + row) * Dd + kc + cc4);
                ys[(cc4 + 0) * (GTJ + 4) + row] = v.x;
                ys[(cc4 + 1) * (GTJ + 4) + row] = v.y;
                ys[(cc4 + 2) * (GTJ + 4) + row] = v.z;
                ys[(cc4 + 3) * (GTJ + 4) + row] = v.w;
            }
            __syncthreads();

            if (t < GTI) {
#pragma unroll
                for (int k = 0; k < KC; k++) {
                    float v = xs[k * (GTI + 4) + t];
                    x2a = fmaf(v, v, x2a);
                }
            } else if (t < GTI + GTJ) {
                int j = t - GTI;
#pragma unroll
                for (int k = 0; k < KC; k++) {
                    float v = ys[k * (GTJ + 4) + j];
                    y2a = fmaf(v, v, y2a);
                }
            }

#pragma unroll
            for (int k = 0; k < KC; k++) {
                float4 av = *reinterpret_cast<const float4*>(&xs[k * (GTI + 4) + r4]);
                float4 b0 = *reinterpret_cast<const float4*>(&ys[k * (GTJ + 4) + c4]);
                unsigned long long b01 = pk2(b0.x, b0.y);
                unsigned long long b23 = pk2(b0.z, b0.w);
                unsigned long long a0 = pk2(av.x, av.x);
                unsigned long long a1 = pk2(av.y, av.y);
                unsigned long long a2 = pk2(av.z, av.z);
                unsigned long long a3 = pk2(av.w, av.w);
                acc[0][0] = ffma2(a0, b01, acc[0][0]); acc[0][1] = ffma2(a0, b23, acc[0][1]);
                acc[1][0] = ffma2(a1, b01, acc[1][0]); acc[1][1] = ffma2(a1, b23, acc[1][1]);
                acc[2][0] = ffma2(a2, b01, acc[2][0]); acc[2][1] = ffma2(a2, b23, acc[2][1]);
                acc[3][0] = ffma2(a3, b01, acc[3][0]); acc[3][1] = ffma2(a3, b23, acc[3][1]);
            }
            __syncthreads();
        }

        if (t < GTI) x2s[t] = x2a;
        else if (t < GTI + GTJ) y2s[t - GTI] = y2a;
        __syncthreads();

#pragma unroll
        for (int r = 0; r < 4; r++) {
            float xr = x2s[r4 + r];
            float a0, a1, a2, a3;
            upk2(acc[r][0], a0, a1); upk2(acc[r][1], a2, a3);
            float4 o;
            o.x = xr + y2s[c4 + 0] - 2.f * a0;
            o.y = xr + y2s[c4 + 1] - 2.f * a1;
            o.z = xr + y2s[c4 + 2] - 2.f * a2;
            o.w = xr + y2s[c4 + 3] - 2.f * a3;
            *reinterpret_cast<float4*>(
                g_C + ((size_t)b * Nn + i0 + r4 + r) * Mn + j0 + c4) = o;
        }

        // publish tile completion (release)
        __threadfence();
        __syncthreads();
        if (t == 0) atomicAdd(&g_cnt[b * NIB + iblk], 1);
        return;
    }

    // =================== DP CTA (batch b, column half c) ===================
    const int b = blockIdx.x >> 1;
    const int c = blockIdx.x & 1;

    if (t >= 512) {
        // helper threads: copy w_ts (each CTA copies its half), then exit.
        float* w_ts = out + Bn;
        int idx = c * 512 + (t - 512);
        w_ts[b * Nn + idx] = x_t[b * Nn + idx];
        return;
    }

    float* wSb  = (float*)smem_raw;                   // [2][16]
    float* wMb  = wSb + 32;                           // [2][16]
    float* qSb  = wMb + 32;                           // [2]
    float* qMb  = qSb + 2;                            // [2]
    float* argV = qMb + 2;                            // [16]
    int*   argJ = (int*)(argV + 16);                  // [16]

    const int lane = t & 31, w = t >> 5;              // 16 warps
    const int j4 = c * 2048 + t * 4;                  // global column base
    const float* Cb = g_C + (size_t)b * Nn * Mn;
    unsigned char* chb = g_choice + (size_t)b * Nn * Mn;
    const bool isCons = (c == 1);
    const bool isProd = (c == 0);

    // gate i-block 0 (t0 acquire, then CTA barrier)
    if (t == 0) {
        while (atomicAdd(&g_cnt[b * NIB + 0], 0) < NJT) __nanosleep(200);
        __threadfence();
    }
    asm volatile("bar.sync 1, 512;" ::: "memory");

    // Row 0: D = C. Register state: pD = D[i-1] own cols; carry = D[i-1][j4-1].
    float4 cc0 = *reinterpret_cast<const float4*>(Cb + j4);
    float pD0 = cc0.x, pD1 = cc0.y, pD2 = cc0.z, pD3 = cc0.w;
    float carry = (j4 == 0) ? INF : Cb[j4 - 1];

    float4 cnA = *reinterpret_cast<const float4*>(Cb + (size_t)1 * Mn + j4);
    float4 cnB = *reinterpret_cast<const float4*>(Cb + (size_t)2 * Mn + j4);

    for (int i = 1; i < Nn; i++) {
        float4 cc;
        if ((i & (IBLK - 1)) == 0) {
            if (t == 0) {
                while (atomicAdd(&g_cnt[b * NIB + (i >> 7)], 0) < NJT) __nanosleep(200);
                __threadfence();
            }
            asm volatile("bar.sync 1, 512;" ::: "memory");
            cc  = *reinterpret_cast<const float4*>(Cb + (size_t)i * Mn + j4);
            cnA = *reinterpret_cast<const float4*>(Cb + (size_t)(i + 1) * Mn + j4);
            cnB = *reinterpret_cast<const float4*>(Cb + (size_t)(i + 2) * Mn + j4);
        } else {
            cc = cnA; cnA = cnB;
            int nf = i + 2;
            if (nf < Nn && (i & (IBLK - 1)) <= IBLK - 3)
                cnB = *reinterpret_cast<const float4*>(Cb + (size_t)nf * Mn + j4);
        }

        // consumer: speculative upstream load, issued before local work
        float qS = 0.f, qM = INF; unsigned tag = (unsigned)i;
        const void* sp = &g_hand[b][i & 255];
        if (isCons && t == 0) ld_pkt(sp, qS, qM, tag);

        // producer backpressure (rare, amortized)
        if (isProd && t == 0 && (i & 63) == 0) {
            while (*((volatile int*)&g_handProg[b]) < i - 128) __nanosleep(200);
        }

        const float up0 = pD0, up1 = pD1, up2 = pD2, up3 = pD3, dg0 = carry;

        float a0 = fminf(up0, dg0) + cc.x;
        float a1 = fminf(up1, up0) + cc.y;
        float a2 = fminf(up2, up1) + cc.z;
        float a3 = fminf(up3, up2) + cc.w;

        float s0 = cc.x, s1 = s0 + cc.y, s2 = s1 + cc.z, s3 = s2 + cc.w;
        float m0 = a0 - s0;
        float m1 = fminf(m0, a1 - s1);
        float m2 = fminf(m1, a2 - s2);
        float m3 = fminf(m2, a3 - s3);

        // warp-level inclusive pair scan: (s,m) op (s',m') = (s+s', min(m, m'-s))
        float S = s3, Mv = m3;
#pragma unroll
        for (int d = 1; d < 32; d <<= 1) {
            float so = __shfl_up_sync(0xffffffffu, S, d);
            float mo = __shfl_up_sync(0xffffffffu, Mv, d);
            if (lane >= d) { Mv = fminf(mo, Mv - so); S = S + so; }
        }
        float sE = __shfl_up_sync(0xffffffffu, S, 1);
        float mE = __shfl_up_sync(0xffffffffu, Mv, 1);
        if (lane == 0) { sE = 0.f; mE = INF; }

        const int par = i & 1;
        if (lane == 31) { wSb[par * 16 + w] = S; wMb[par * 16 + w] = Mv; }

        // consumer t0: finish the upstream wait (pure spin, no sleep) and
        // broadcast Q through smem; overlapped with other warps reaching bar.
        if (isCons && t == 0) {
            while (tag != (unsigned)i) ld_pkt(sp, qS, qM, tag);
            qSb[par] = qS; qMb[par] = qM;
            if ((i & 63) == 0) *((volatile int*)&g_handProg[b]) = i;
        }
        asm volatile("bar.sync 1, 512;" ::: "memory");   // the ONLY barrier/row

        // redundant level-2 scan over the 16 warp aggregates (every warp)
        float Sw = wSb[par * 16 + (lane & 15)];
        float Mw = wMb[par * 16 + (lane & 15)];
#pragma unroll
        for (int d = 1; d < 16; d <<= 1) {
            float so = __shfl_up_sync(0xffffffffu, Sw, d);
            float mo = __shfl_up_sync(0xffffffffu, Mw, d);
            if ((lane & 15) >= d && lane < 16) { Mw = fminf(mo, Mw - so); Sw = Sw + so; }
        }
        float Sg = 0.f, Mg = INF;
        if (w > 0) {
            Sg = __shfl_sync(0xffffffffu, Sw, w - 1);
            Mg = __shfl_sync(0xffffffffu, Mw, w - 1);
        }
        if (isCons) { qS = qSb[par]; qM = qMb[par]; }   // all threads read Q

        // global exclusive prefix: Q o (CTA-exclusive)
        float SexC = Sg + sE;
        float MexC = fminf(Mg, mE - Sg);
        float offS = qS + SexC;
        float PexM = fminf(qM, MexC - qS);

        // producer t0: publish Q o (CTA inclusive total) downstream
        if (isProd && lane < 16) {
            float S15 = __shfl_sync(0x0000ffffu, Sw, 15, 16);
            float M15 = __shfl_sync(0x0000ffffu, Mw, 15, 16);
            if (t == 0) st_pkt(&g_hand[b][i & 255], S15, M15, (unsigned)i);
        }

        float D0 = offS + s0 + fminf(PexM, m0 - offS);
        float D1 = offS + s1 + fminf(PexM, m1 - offS);
        float D2 = offS + s2 + fminf(PexM, m2 - offS);
        float D3 = offS + s3 + fminf(PexM, m3 - offS);

        float dl0 = offS + PexM;            // == D[i][j4-1] (INF at global col 0)

        // choice codes: 0=diag, 1=up, 2=left (tie priority diag > up > left)
        unsigned char q0 = (dg0 <= up0 && dg0 <= dl0) ? 0 : ((up0 <= dl0) ? 1 : 2);
        unsigned char q1 = (up0 <= up1 && up0 <= D0)  ? 0 : ((up1 <= D0)  ? 1 : 2);
        unsigned char q2 = (up1 <= up2 && up1 <= D1)  ? 0 : ((up2 <= D1)  ? 1 : 2);
        unsigned char q3 = (up2 <= up3 && up2 <= D2)  ? 0 : ((up3 <= D2)  ? 1 : 2);

        *reinterpret_cast<uchar4*>(chb + chaddr(i, j4)) = make_uchar4(q0, q1, q2, q3);

        pD0 = D0; pD1 = D1; pD2 = D2; pD3 = D3;
        carry = dl0;
    }

    // argmin (first occurrence) over last row: registers -> warp -> CTA -> pair
    float bv = pD0; int bj = j4;
    if (pD1 < bv) { bv = pD1; bj = j4 + 1; }
    if (pD2 < bv) { bv = pD2; bj = j4 + 2; }
    if (pD3 < bv) { bv = pD3; bj = j4 + 3; }
#pragma unroll
    for (int d = 16; d > 0; d >>= 1) {
        float ov = __shfl_xor_sync(0xffffffffu, bv, d);
        int   oj = __shfl_xor_sync(0xffffffffu, bj, d);
        if (ov < bv || (ov == bv && oj < bj)) { bv = ov; bj = oj; }
    }
    if (lane == 0) { argV[w] = bv; argJ[w] = bj; }
    asm volatile("bar.sync 1, 512;" ::: "memory");

    if (w == 0) {
        float v = INF; int jj = 0x7fffffff;
        if (lane < 16) { v = argV[lane]; jj = argJ[lane]; }
#pragma unroll
        for (int d = 16; d > 0; d >>= 1) {
            float ov = __shfl_xor_sync(0xffffffffu, v, d);
            int   oj = __shfl_xor_sync(0xffffffffu, jj, d);
            if (ov < v || (ov == v && oj < jj)) { v = ov; jj = oj; }
        }
        if (lane == 0) {
            st_pktu(&g_part[b][c], __float_as_uint(v), (unsigned)jj, 1u);
            if (c == 0) {
                unsigned a, b2, tg;
                ld_pktu(&g_part[b][1], a, b2, tg);
                while (tg != 1u) { __nanosleep(100); ld_pktu(&g_part[b][1], a, b2, tg); }
                float v1 = __uint_as_float(a);
                if (v1 < v) { v = v1; jj = (int)b2; }   // ties keep c0 (smaller j)
                out[b] = v;
                g_j0[b] = jj;
            }
        }
    }
}

// ---------------------------------------------------------------------------
// Band-parallel backtrack precompute: for every (batch, band tb in [1,31],
// entry column j) walk the 32-row segment; record exit column.
// ---------------------------------------------------------------------------
__global__ void __launch_bounds__(256) bandwalk_kernel() {
    const int tb = blockIdx.x + 1;               // 1..31
    const int b  = blockIdx.y;
    const unsigned char* chb = g_choice + (size_t)b * Nn * Mn;
    const int iTop  = tb * 32 + 31;
    const int iStop = tb * 32 - 1;               // walk while i > iStop

#pragma unroll
    for (int k = 0; k < Mn / 256; k++) {
        int j = threadIdx.x + k * 256;
        int jin = j;
        int i = iTop;
        while (i > iStop) {
            unsigned char ch = __ldg(chb + chaddr(i, j));
            if (ch == 0)      { --i; --j; }
            else if (ch == 1) { --i; }
            else              { --j; }
        }
        g_exitJ[b][tb][jin] = (unsigned short)j;
    }
}

// ---------------------------------------------------------------------------
// Finalize: per batch, chain band entry columns through the exit table, then
// 32 parallel segment re-walks emit w_vs.
// ---------------------------------------------------------------------------
__global__ void __launch_bounds__(64) finalize_kernel(const float* __restrict__ y_t,
                                                      float* __restrict__ out) {
    __shared__ int entry[NBAND];
    const int b = blockIdx.x, t = threadIdx.x;
    float* w_vs = out + Bn + Bn * Nn;
    const float* ytb = y_t + (size_t)b * Mn;
    const unsigned char* chb = g_choice + (size_t)b * Nn * Mn;

    if (t == 0) {
        int j = g_j0[b];
        w_vs[b * Nn + (Nn - 1)] = ytb[j];        // row 1023 entry
        entry[NBAND - 1] = j;
        for (int tb = NBAND - 1; tb >= 1; --tb) {
            j = g_exitJ[b][tb][j];
            entry[tb - 1] = j;
        }
    }
    __syncthreads();

    if (t < NBAND) {
        const int tb = t;
        int i = tb * 32 + 31;
        int j = entry[tb];
        const int iStop = (tb == 0) ? 0 : (tb * 32 - 1);
        while (i > iStop) {
            unsigned char ch = __ldg(chb + chaddr(i, j));
            if (ch == 2) { --j; }
            else {
                if (ch == 0) --j;
                --i;
                w_vs[b * Nn + i] = ytb[j];
            }
        }
    }
}

// ---------------------------------------------------------------------------
extern "C" void kernel_launch(void* const* d_in, const int* in_sizes, int n_in,
                              void* d_out, int out_size) {
    const float* x   = (const float*)d_in[0];   // [16,1024,64]
    const float* y   = (const float*)d_in[1];   // [16,4096,64]
    const float* x_t = (const float*)d_in[2];   // [16,1024]
    const float* y_t = (const float*)d_in[3];   // [16,4096]
    float* out = (float*)d_out;                 // 16 + 16384 + 16384 floats

    zero_cnt_kernel<<<1, 1024>>>();
    fused_kernel<<<NDPC + Bn * NIB * NJT, 1024>>>(x, y, x_t, out);
    bandwalk_kernel<<<dim3(NBAND - 1, Bn), 256>>>();
    finalize_kernel<<<Bn, 64>>>(y_t, out);
}